// round 11
// baseline (speedup 1.0000x reference)
#include <cuda_runtime.h>
#include <cstdint>

// Embedding gather: out[r, :] = weight[ids[r], :]
// weight: [50257, 1024] fp32, ids: [32768] int32, out: [32768, 1024] fp32
//
// R11: write-path experiment. R6/R7/R9/R10 all plateau at ~188MB DRAM bytes
// per launch (~60MB warm read misses despite the ~98MB hot row set fitting
// the 126MB L2). Hypothesis: the 128MB write-once output stream ALLOCATES L2
// lines (.cs evict-first notwithstanding) and evicts hot weight rows.
// Change vs R10 (single variable): stores become st.global.wt -> write
// through, no L2 capacity claim. Loads unchanged (16B gathers + evict_last
// policy hint, 8 rows/CTA, 256 threads, regs~32, occ~79%).

#define DIM4 256          // DIM/4 float4 per row
#define THREADS 256
#define ROWS_PER_CTA 8

__global__ __launch_bounds__(THREADS)
void embed_gather_kernel(const float4* __restrict__ weight,
                         const int* __restrict__ ids,
                         float4* __restrict__ out,
                         int n_rows)
{
    const int tid  = threadIdx.x;
    const int base = blockIdx.x * ROWS_PER_CTA;

    // L2 policy: evict_last for the gathered weight rows
    uint64_t policy;
    asm("createpolicy.fractional.L2::evict_last.b64 %0, 1.0;" : "=l"(policy));

    // 8 independent broadcast index loads
    int idx[ROWS_PER_CTA];
#pragma unroll
    for (int r = 0; r < ROWS_PER_CTA; r++)
        idx[r] = ids[base + r];

    // 8 independent 16B gathers with evict_last cache hint
    float v[ROWS_PER_CTA][4];
#pragma unroll
    for (int r = 0; r < ROWS_PER_CTA; r++) {
        const float4* src = weight + (size_t)idx[r] * DIM4 + tid;
        asm("ld.global.nc.L2::cache_hint.v4.f32 {%0, %1, %2, %3}, [%4], %5;"
            : "=f"(v[r][0]), "=f"(v[r][1]), "=f"(v[r][2]), "=f"(v[r][3])
            : "l"(src), "l"(policy));
    }

    // 8 write-through stores: no L2 allocation for the write-once output
#pragma unroll
    for (int r = 0; r < ROWS_PER_CTA; r++) {
        float4* dst = out + (size_t)(base + r) * DIM4 + tid;
        asm volatile("st.global.wt.v4.f32 [%0], {%1, %2, %3, %4};"
                     :: "l"(dst),
                        "f"(v[r][0]), "f"(v[r][1]), "f"(v[r][2]), "f"(v[r][3])
                     : "memory");
    }
}

extern "C" void kernel_launch(void* const* d_in, const int* in_sizes, int n_in,
                              void* d_out, int out_size)
{
    // Identify inputs by element count:
    //   weight: 50257*1024 = 51463168 elements; ids: 32768 elements
    const float4* weight;
    const int* ids;
    int n_rows;

    if (in_sizes[0] > in_sizes[1]) {
        weight = (const float4*)d_in[0];
        ids    = (const int*)d_in[1];
        n_rows = in_sizes[1];
    } else {
        weight = (const float4*)d_in[1];
        ids    = (const int*)d_in[0];
        n_rows = in_sizes[0];
    }

    int n_blocks = n_rows / ROWS_PER_CTA;  // 32768/8 = 4096, exact
    embed_gather_kernel<<<n_blocks, THREADS>>>(weight, ids, (float4*)d_out, n_rows);
}